// round 3
// baseline (speedup 1.0000x reference)
#include <cuda_runtime.h>

// Shapes fixed by the problem
#define B_DIM 512
#define T_DIM 400
#define V_DIM 32000
#define ENC_DIM 1024
#define HID_DIM 1024
#define EMB_DIM 512

#define SLICES 4                       // column slices per row
#define SLICE_F (V_DIM / SLICES)       // 8000 floats per slice
#define SLICE_F4 (SLICE_F / 4)         // 2000 float4 per slice
#define NT2 256                        // threads in main kernel
#define BATCH 8                        // float4 per thread (7 full + 1 partial)

__device__ float g_pgen[B_DIM];

// ---------------------------------------------------------------------------
// Kernel 1: per-row p_gen = sigmoid(context.w_c + state.w_s + emb.w_y + b)
// ---------------------------------------------------------------------------
__global__ __launch_bounds__(256)
void pgen_kernel(
    const float* __restrict__ context,  // [B, ENC]
    const float* __restrict__ state,    // [B, HID]
    const float* __restrict__ emb,      // [B, EMB]
    const float* __restrict__ w_c,      // [ENC]
    const float* __restrict__ w_s,      // [HID]
    const float* __restrict__ w_y,      // [EMB]
    const float* __restrict__ b_p)      // [1]
{
    const int row = blockIdx.x;
    const int tid = threadIdx.x;

    float acc = 0.0f;

    {
        const float4 a = reinterpret_cast<const float4*>(context + (size_t)row * ENC_DIM)[tid];
        const float4 w = reinterpret_cast<const float4*>(w_c)[tid];
        acc += a.x * w.x + a.y * w.y + a.z * w.z + a.w * w.w;
    }
    {
        const float4 a = reinterpret_cast<const float4*>(state + (size_t)row * HID_DIM)[tid];
        const float4 w = reinterpret_cast<const float4*>(w_s)[tid];
        acc += a.x * w.x + a.y * w.y + a.z * w.z + a.w * w.w;
    }
    if (tid < EMB_DIM / 4) {
        const float4 a = reinterpret_cast<const float4*>(emb + (size_t)row * EMB_DIM)[tid];
        const float4 w = reinterpret_cast<const float4*>(w_y)[tid];
        acc += a.x * w.x + a.y * w.y + a.z * w.z + a.w * w.w;
    }

    #pragma unroll
    for (int off = 16; off > 0; off >>= 1)
        acc += __shfl_down_sync(0xffffffffu, acc, off);

    __shared__ float s_partial[8];
    const int lane = tid & 31;
    const int wid  = tid >> 5;
    if (lane == 0) s_partial[wid] = acc;
    __syncthreads();
    if (tid == 0) {
        float total = 0.0f;
        #pragma unroll
        for (int i = 0; i < 8; i++) total += s_partial[i];
        total += b_p[0];
        g_pgen[row] = 1.0f / (1.0f + __expf(-total));
    }
}

// ---------------------------------------------------------------------------
// Kernel 2: loads vocab slice FIRST (independent of pgen), then PDL-waits on
//           kernel 1, then scales + stores + slice-restricted scatter-add.
//           __launch_bounds__(256,4) -> 64-reg budget so the 8xfloat4 batch
//           truly resides in registers (real MLP, not serialized pairs).
// ---------------------------------------------------------------------------
__global__ __launch_bounds__(NT2, 4)
void scale_scatter_kernel(
    const float* __restrict__ vocab_dist,   // [B, V]
    const float* __restrict__ attn_dist,    // [B, T]
    const int*   __restrict__ src_ids,      // [B, T]
    const int*   __restrict__ vocab_size_p, // scalar
    float*       __restrict__ out)          // [B, V]
{
    const int bid   = blockIdx.x;
    const int row   = bid >> 2;      // SLICES == 4
    const int slice = bid & 3;
    const int tid   = threadIdx.x;

    const float4* v4 = reinterpret_cast<const float4*>(vocab_dist + (size_t)row * V_DIM) + slice * SLICE_F4;
    float4*       o4 = reinterpret_cast<float4*>(out + (size_t)row * V_DIM) + slice * SLICE_F4;

    // ---- Front-batched loads (independent of pgen kernel) ----
    float4 r[BATCH];
    #pragma unroll
    for (int k = 0; k < BATCH - 1; k++)
        r[k] = v4[tid + k * NT2];
    const bool has_last = tid < (SLICE_F4 - (BATCH - 1) * NT2);   // tid < 208
    if (has_last)
        r[BATCH - 1] = v4[tid + (BATCH - 1) * NT2];

    const int vsz = *vocab_size_p;   // also independent of pgen

    // ---- Wait for pgen kernel (PDL): hides its entire duration ----
    cudaGridDependencySynchronize();

    const float pg = g_pgen[row];
    const float pc = 1.0f - pg;

    // ---- Scale + evict-first stores ----
    #pragma unroll
    for (int k = 0; k < BATCH - 1; k++) {
        float4 x = r[k];
        x.x *= pg; x.y *= pg; x.z *= pg; x.w *= pg;
        __stcs(o4 + tid + k * NT2, x);
    }
    if (has_last) {
        float4 x = r[BATCH - 1];
        x.x *= pg; x.y *= pg; x.z *= pg; x.w *= pg;
        __stcs(o4 + tid + (BATCH - 1) * NT2, x);
    }

    // Block-scope ordering: this CTA's stores visible to this CTA's atomics.
    __syncthreads();

    // ---- Masked scatter-add restricted to this slice's columns ----
    const int lo  = slice * SLICE_F;
    const int hi  = lo + SLICE_F;
    const int*   ids = src_ids   + (size_t)row * T_DIM;
    const float* at  = attn_dist + (size_t)row * T_DIM;

    #pragma unroll
    for (int t = tid; t < T_DIM; t += NT2) {
        const int id = ids[t];
        if (id < vsz && id >= lo && id < hi) {
            atomicAdd(out + (size_t)row * V_DIM + id, pc * at[t]);
        }
    }
}

extern "C" void kernel_launch(void* const* d_in, const int* in_sizes, int n_in,
                              void* d_out, int out_size) {
    const float* vocab_dist = (const float*)d_in[0];
    const float* attn_dist  = (const float*)d_in[1];
    const float* context    = (const float*)d_in[2];
    const float* state      = (const float*)d_in[3];
    const float* emb        = (const float*)d_in[4];
    const int*   src_ids    = (const int*)d_in[5];
    const int*   vocab_size = (const int*)d_in[6];
    const float* w_c        = (const float*)d_in[7];
    const float* w_s        = (const float*)d_in[8];
    const float* w_y        = (const float*)d_in[9];
    const float* b          = (const float*)d_in[10];
    float*       out        = (float*)d_out;

    // Kernel 1: plain launch
    pgen_kernel<<<B_DIM, 256>>>(context, state, emb, w_c, w_s, w_y, b);

    // Kernel 2: launched with Programmatic Stream Serialization so it starts
    // while kernel 1 runs; the in-kernel cudaGridDependencySynchronize()
    // provides the ordering before g_pgen is read.
    cudaLaunchConfig_t cfg = {};
    cfg.gridDim  = dim3(B_DIM * SLICES, 1, 1);
    cfg.blockDim = dim3(NT2, 1, 1);
    cfg.dynamicSmemBytes = 0;
    cfg.stream = 0;
    cudaLaunchAttribute attrs[1];
    attrs[0].id = cudaLaunchAttributeProgrammaticStreamSerialization;
    attrs[0].val.programmaticStreamSerializationAllowed = 1;
    cfg.attrs = attrs;
    cfg.numAttrs = 1;

    cudaLaunchKernelEx(&cfg, scale_scatter_kernel,
                       vocab_dist, attn_dist, src_ids, vocab_size, out);
}

// round 4
// speedup vs baseline: 1.1694x; 1.1694x over previous
#include <cuda_runtime.h>

// Shapes fixed by the problem
#define B_DIM 512
#define T_DIM 400
#define V_DIM 32000
#define ENC_DIM 1024
#define HID_DIM 1024
#define EMB_DIM 512

#define SLICES 4                       // column slices per row
#define SLICE_F (V_DIM / SLICES)       // 8000 floats per slice
#define SLICE_F4 (SLICE_F / 4)         // 2000 float4 per slice
#define NT 256                         // threads per CTA
#define BATCH 8                        // float4 per thread (7 full + 1 partial)

// ---------------------------------------------------------------------------
// Single fused kernel. Each CTA owns one (row, slice):
//   1. redundantly computes the row's p_gen (L2-amortized across the 4 slices)
//   2. streams its vocab slice: out = p_gen * vocab   (evict-first stores)
//   3. scatter-adds (1-p_gen)*attn for src_ids landing in ITS slice
// The intra-CTA __syncthreads() between (2) and (3) provides the required
// store->atomic ordering; slicing removes all cross-CTA hazards.
// ---------------------------------------------------------------------------
__global__ __launch_bounds__(NT)
void pointer_generator_fused(
    const float* __restrict__ vocab_dist,   // [B, V]
    const float* __restrict__ attn_dist,    // [B, T]
    const float* __restrict__ context,      // [B, ENC]
    const float* __restrict__ state,        // [B, HID]
    const float* __restrict__ emb,          // [B, EMB]
    const int*   __restrict__ src_ids,      // [B, T]
    const int*   __restrict__ vocab_size_p, // scalar
    const float* __restrict__ w_c,          // [ENC]
    const float* __restrict__ w_s,          // [HID]
    const float* __restrict__ w_y,          // [EMB]
    const float* __restrict__ b_p,          // [1]
    float*       __restrict__ out)          // [B, V]
{
    const int bid   = blockIdx.x;
    const int row   = bid >> 2;      // SLICES == 4
    const int slice = bid & 3;
    const int tid   = threadIdx.x;

    // ---------------- Phase 1: p_gen (redundant per slice-CTA) ----------------
    float acc = 0.0f;
    {
        const float4 a = reinterpret_cast<const float4*>(context + (size_t)row * ENC_DIM)[tid];
        const float4 w = reinterpret_cast<const float4*>(w_c)[tid];
        acc += a.x * w.x + a.y * w.y + a.z * w.z + a.w * w.w;
    }
    {
        const float4 a = reinterpret_cast<const float4*>(state + (size_t)row * HID_DIM)[tid];
        const float4 w = reinterpret_cast<const float4*>(w_s)[tid];
        acc += a.x * w.x + a.y * w.y + a.z * w.z + a.w * w.w;
    }
    if (tid < EMB_DIM / 4) {
        const float4 a = reinterpret_cast<const float4*>(emb + (size_t)row * EMB_DIM)[tid];
        const float4 w = reinterpret_cast<const float4*>(w_y)[tid];
        acc += a.x * w.x + a.y * w.y + a.z * w.z + a.w * w.w;
    }

    #pragma unroll
    for (int off = 16; off > 0; off >>= 1)
        acc += __shfl_down_sync(0xffffffffu, acc, off);

    __shared__ float s_partial[NT / 32];
    __shared__ float s_pgen;
    const int lane = tid & 31;
    const int wid  = tid >> 5;
    if (lane == 0) s_partial[wid] = acc;
    __syncthreads();
    if (tid == 0) {
        float total = 0.0f;
        #pragma unroll
        for (int i = 0; i < NT / 32; i++) total += s_partial[i];
        total += b_p[0];
        s_pgen = 1.0f / (1.0f + __expf(-total));
    }
    __syncthreads();

    const float pg = s_pgen;
    const float pc = 1.0f - pg;

    // ---------------- Phase 2: stream the vocab slice ----------------
    const float4* v4 = reinterpret_cast<const float4*>(vocab_dist + (size_t)row * V_DIM) + slice * SLICE_F4;
    float4*       o4 = reinterpret_cast<float4*>(out + (size_t)row * V_DIM) + slice * SLICE_F4;

    #pragma unroll
    for (int k = 0; k < BATCH - 1; k++) {
        float4 x = v4[tid + k * NT];
        x.x *= pg; x.y *= pg; x.z *= pg; x.w *= pg;
        __stcs(o4 + tid + k * NT, x);   // evict-first: keep vocab_dist L2-resident
    }
    if (tid < (SLICE_F4 - (BATCH - 1) * NT)) {   // tid < 208
        float4 x = v4[tid + (BATCH - 1) * NT];
        x.x *= pg; x.y *= pg; x.z *= pg; x.w *= pg;
        __stcs(o4 + tid + (BATCH - 1) * NT, x);
    }

    // Block-scope ordering: this CTA's stores visible to this CTA's atomics.
    __syncthreads();

    // ---------------- Phase 3: slice-restricted masked scatter-add ----------------
    const int vsz = *vocab_size_p;
    const int lo  = slice * SLICE_F;
    const int hi  = lo + SLICE_F;
    const int*   ids = src_ids   + (size_t)row * T_DIM;
    const float* at  = attn_dist + (size_t)row * T_DIM;

    #pragma unroll
    for (int t = tid; t < T_DIM; t += NT) {
        const int id = ids[t];
        if (id < vsz && id >= lo && id < hi) {
            atomicAdd(out + (size_t)row * V_DIM + id, pc * at[t]);
        }
    }
}

extern "C" void kernel_launch(void* const* d_in, const int* in_sizes, int n_in,
                              void* d_out, int out_size) {
    const float* vocab_dist = (const float*)d_in[0];
    const float* attn_dist  = (const float*)d_in[1];
    const float* context    = (const float*)d_in[2];
    const float* state      = (const float*)d_in[3];
    const float* emb        = (const float*)d_in[4];
    const int*   src_ids    = (const int*)d_in[5];
    const int*   vocab_size = (const int*)d_in[6];
    const float* w_c        = (const float*)d_in[7];
    const float* w_s        = (const float*)d_in[8];
    const float* w_y        = (const float*)d_in[9];
    const float* b          = (const float*)d_in[10];
    float*       out        = (float*)d_out;

    pointer_generator_fused<<<B_DIM * SLICES, NT>>>(
        vocab_dist, attn_dist, context, state, emb, src_ids, vocab_size,
        w_c, w_s, w_y, b, out);
}

// round 5
// speedup vs baseline: 1.2517x; 1.0704x over previous
#include <cuda_runtime.h>

// Shapes fixed by the problem
#define B_DIM 512
#define T_DIM 400
#define V_DIM 32000
#define ENC_DIM 1024
#define HID_DIM 1024
#define EMB_DIM 512

#define SLICES 2                       // column slices per row
#define SLICE_F (V_DIM / SLICES)       // 16000 floats per slice
#define SLICE_F4 (SLICE_F / 4)         // 4000 float4 per slice
#define NT 256                         // threads per CTA
#define FULL_ITERS (SLICE_F4 / NT)     // 15 full passes
#define TAIL (SLICE_F4 - FULL_ITERS * NT)  // 160 threads in tail

// ---------------------------------------------------------------------------
// Single fused kernel, 1024 CTAs (all-resident in one wave at 8 CTAs/SM).
// Each CTA owns one (row, slice):
//   1. redundantly computes the row's p_gen (2x redundancy, L2-amortized)
//   2. streams its vocab slice: out = p_gen * vocab   (evict-first stores)
//   3. scatter-adds (1-p_gen)*attn for src_ids landing in ITS slice
// Intra-CTA __syncthreads() between (2) and (3) orders store -> atomic;
// slicing removes all cross-CTA hazards.
// ---------------------------------------------------------------------------
__global__ __launch_bounds__(NT)
void pointer_generator_fused(
    const float* __restrict__ vocab_dist,   // [B, V]
    const float* __restrict__ attn_dist,    // [B, T]
    const float* __restrict__ context,      // [B, ENC]
    const float* __restrict__ state,        // [B, HID]
    const float* __restrict__ emb,          // [B, EMB]
    const int*   __restrict__ src_ids,      // [B, T]
    const int*   __restrict__ vocab_size_p, // scalar
    const float* __restrict__ w_c,          // [ENC]
    const float* __restrict__ w_s,          // [HID]
    const float* __restrict__ w_y,          // [EMB]
    const float* __restrict__ b_p,          // [1]
    float*       __restrict__ out)          // [B, V]
{
    const int bid   = blockIdx.x;
    const int row   = bid >> 1;      // SLICES == 2
    const int slice = bid & 1;
    const int tid   = threadIdx.x;

    // ---------------- Phase 1: p_gen (2x redundant, L2-amortized) ----------------
    float acc = 0.0f;
    {
        const float4 a = reinterpret_cast<const float4*>(context + (size_t)row * ENC_DIM)[tid];
        const float4 w = reinterpret_cast<const float4*>(w_c)[tid];
        acc += a.x * w.x + a.y * w.y + a.z * w.z + a.w * w.w;
    }
    {
        const float4 a = reinterpret_cast<const float4*>(state + (size_t)row * HID_DIM)[tid];
        const float4 w = reinterpret_cast<const float4*>(w_s)[tid];
        acc += a.x * w.x + a.y * w.y + a.z * w.z + a.w * w.w;
    }
    if (tid < EMB_DIM / 4) {
        const float4 a = reinterpret_cast<const float4*>(emb + (size_t)row * EMB_DIM)[tid];
        const float4 w = reinterpret_cast<const float4*>(w_y)[tid];
        acc += a.x * w.x + a.y * w.y + a.z * w.z + a.w * w.w;
    }

    #pragma unroll
    for (int off = 16; off > 0; off >>= 1)
        acc += __shfl_down_sync(0xffffffffu, acc, off);

    __shared__ float s_partial[NT / 32];
    __shared__ float s_pgen;
    const int lane = tid & 31;
    const int wid  = tid >> 5;
    if (lane == 0) s_partial[wid] = acc;
    __syncthreads();
    if (tid == 0) {
        float total = 0.0f;
        #pragma unroll
        for (int i = 0; i < NT / 32; i++) total += s_partial[i];
        total += b_p[0];
        s_pgen = 1.0f / (1.0f + __expf(-total));
    }
    __syncthreads();

    const float pg = s_pgen;
    const float pc = 1.0f - pg;

    // ---------------- Phase 2: stream the vocab slice ----------------
    const float4* v4 = reinterpret_cast<const float4*>(vocab_dist + (size_t)row * V_DIM) + slice * SLICE_F4;
    float4*       o4 = reinterpret_cast<float4*>(out + (size_t)row * V_DIM) + slice * SLICE_F4;

    #pragma unroll 5
    for (int k = 0; k < FULL_ITERS; k++) {
        float4 x = v4[tid + k * NT];
        x.x *= pg; x.y *= pg; x.z *= pg; x.w *= pg;
        __stcs(o4 + tid + k * NT, x);   // evict-first: drain writes promptly
    }
    if (tid < TAIL) {
        float4 x = v4[tid + FULL_ITERS * NT];
        x.x *= pg; x.y *= pg; x.z *= pg; x.w *= pg;
        __stcs(o4 + tid + FULL_ITERS * NT, x);
    }

    // Block-scope ordering: this CTA's stores visible to this CTA's atomics.
    __syncthreads();

    // ---------------- Phase 3: slice-restricted masked scatter-add ----------------
    const int vsz = *vocab_size_p;
    const int lo  = slice * SLICE_F;
    const int hi  = lo + SLICE_F;
    const int*   ids = src_ids   + (size_t)row * T_DIM;
    const float* at  = attn_dist + (size_t)row * T_DIM;

    #pragma unroll
    for (int t = tid; t < T_DIM; t += NT) {
        const int id = ids[t];
        if (id < vsz && id >= lo && id < hi) {
            atomicAdd(out + (size_t)row * V_DIM + id, pc * at[t]);
        }
    }
}

extern "C" void kernel_launch(void* const* d_in, const int* in_sizes, int n_in,
                              void* d_out, int out_size) {
    const float* vocab_dist = (const float*)d_in[0];
    const float* attn_dist  = (const float*)d_in[1];
    const float* context    = (const float*)d_in[2];
    const float* state      = (const float*)d_in[3];
    const float* emb        = (const float*)d_in[4];
    const int*   src_ids    = (const int*)d_in[5];
    const int*   vocab_size = (const int*)d_in[6];
    const float* w_c        = (const float*)d_in[7];
    const float* w_s        = (const float*)d_in[8];
    const float* w_y        = (const float*)d_in[9];
    const float* b          = (const float*)d_in[10];
    float*       out        = (float*)d_out;

    pointer_generator_fused<<<B_DIM * SLICES, NT>>>(
        vocab_dist, attn_dist, context, state, emb, src_ids, vocab_size,
        w_c, w_s, w_y, b, out);
}

// round 8
// speedup vs baseline: 1.2865x; 1.0278x over previous
#include <cuda_runtime.h>
#include <cstdint>

// Shapes fixed by the problem
#define B_DIM 512
#define T_DIM 400
#define V_DIM 32000
#define ENC_DIM 1024
#define HID_DIM 1024
#define EMB_DIM 512

#define SLICES 2                        // column slices per row
#define SLICE_F (V_DIM / SLICES)        // 16000 floats per slice
#define SLICE_F8 (SLICE_F / 8)          // 2000 float8 per slice
#define NT 256                          // threads per CTA
#define FULL_ITERS (SLICE_F8 / NT)      // 7 full passes
#define TAIL (SLICE_F8 - FULL_ITERS * NT)   // 208 threads in tail

// sm_103a: L2 eviction-priority hints require 256-bit (.v8.b32) accesses.
// vocab_dist is re-read every graph replay -> evict_last pins it L2-resident;
// out is write-once -> evict_first makes its lines the preferred victims.
struct F8 { uint32_t r[8]; };

__device__ __forceinline__ F8 ldg256_evict_last(const float* p) {
    F8 v;
    asm volatile("ld.global.nc.L2::evict_last.v8.b32 {%0,%1,%2,%3,%4,%5,%6,%7}, [%8];"
                 : "=r"(v.r[0]), "=r"(v.r[1]), "=r"(v.r[2]), "=r"(v.r[3]),
                   "=r"(v.r[4]), "=r"(v.r[5]), "=r"(v.r[6]), "=r"(v.r[7])
                 : "l"(p));
    return v;
}
__device__ __forceinline__ void stg256_evict_first(float* p, const F8& v) {
    asm volatile("st.global.L2::evict_first.v8.b32 [%0], {%1,%2,%3,%4,%5,%6,%7,%8};"
                 :: "l"(p),
                    "r"(v.r[0]), "r"(v.r[1]), "r"(v.r[2]), "r"(v.r[3]),
                    "r"(v.r[4]), "r"(v.r[5]), "r"(v.r[6]), "r"(v.r[7])
                 : "memory");
}

// ---------------------------------------------------------------------------
// Single fused kernel, 1024 CTAs, one fully-resident wave (8 CTAs/SM pinned).
// Each CTA owns one (row, slice):
//   1. redundantly computes the row's p_gen (2x redundancy, L2-amortized)
//   2. streams its vocab slice with 256-bit accesses:
//        out = p_gen * vocab   (evict_last reads, evict_first stores)
//   3. scatter-adds (1-p_gen)*attn for src_ids landing in ITS slice
// Intra-CTA __syncthreads() between (2) and (3) orders store -> atomic;
// slicing removes all cross-CTA hazards.
// ---------------------------------------------------------------------------
__global__ __launch_bounds__(NT, 8)
void pointer_generator_fused(
    const float* __restrict__ vocab_dist,   // [B, V]
    const float* __restrict__ attn_dist,    // [B, T]
    const float* __restrict__ context,      // [B, ENC]
    const float* __restrict__ state,        // [B, HID]
    const float* __restrict__ emb,          // [B, EMB]
    const int*   __restrict__ src_ids,      // [B, T]
    const int*   __restrict__ vocab_size_p, // scalar
    const float* __restrict__ w_c,          // [ENC]
    const float* __restrict__ w_s,          // [HID]
    const float* __restrict__ w_y,          // [EMB]
    const float* __restrict__ b_p,          // [1]
    float*       __restrict__ out)          // [B, V]
{
    const int bid   = blockIdx.x;
    const int row   = bid >> 1;      // SLICES == 2
    const int slice = bid & 1;
    const int tid   = threadIdx.x;

    // ---------------- Phase 1: p_gen (2x redundant, L2-amortized) ----------------
    float acc = 0.0f;
    {
        const float4 a = reinterpret_cast<const float4*>(context + (size_t)row * ENC_DIM)[tid];
        const float4 w = reinterpret_cast<const float4*>(w_c)[tid];
        acc += a.x * w.x + a.y * w.y + a.z * w.z + a.w * w.w;
    }
    {
        const float4 a = reinterpret_cast<const float4*>(state + (size_t)row * HID_DIM)[tid];
        const float4 w = reinterpret_cast<const float4*>(w_s)[tid];
        acc += a.x * w.x + a.y * w.y + a.z * w.z + a.w * w.w;
    }
    if (tid < EMB_DIM / 4) {
        const float4 a = reinterpret_cast<const float4*>(emb + (size_t)row * EMB_DIM)[tid];
        const float4 w = reinterpret_cast<const float4*>(w_y)[tid];
        acc += a.x * w.x + a.y * w.y + a.z * w.z + a.w * w.w;
    }

    #pragma unroll
    for (int off = 16; off > 0; off >>= 1)
        acc += __shfl_down_sync(0xffffffffu, acc, off);

    __shared__ float s_partial[NT / 32];
    const int lane = tid & 31;
    const int wid  = tid >> 5;
    if (lane == 0) s_partial[wid] = acc;
    __syncthreads();

    // Every thread sums the 8 warp partials itself (broadcast LDS, no 2nd barrier).
    float total = b_p[0];
    #pragma unroll
    for (int i = 0; i < NT / 32; i++) total += s_partial[i];
    const float pg = 1.0f / (1.0f + __expf(-total));
    const float pc = 1.0f - pg;

    // ---------------- Phase 2: stream the vocab slice (256-bit) ----------------
    const float* vbase = vocab_dist + (size_t)row * V_DIM + slice * SLICE_F;
    float*       obase = out        + (size_t)row * V_DIM + slice * SLICE_F;

    #pragma unroll 2
    for (int k = 0; k < FULL_ITERS; k++) {
        const int idx = (tid + k * NT) * 8;
        F8 x = ldg256_evict_last(vbase + idx);
        #pragma unroll
        for (int j = 0; j < 8; j++)
            x.r[j] = __float_as_uint(pg * __uint_as_float(x.r[j]));
        stg256_evict_first(obase + idx, x);
    }
    if (tid < TAIL) {
        const int idx = (tid + FULL_ITERS * NT) * 8;
        F8 x = ldg256_evict_last(vbase + idx);
        #pragma unroll
        for (int j = 0; j < 8; j++)
            x.r[j] = __float_as_uint(pg * __uint_as_float(x.r[j]));
        stg256_evict_first(obase + idx, x);
    }

    // Block-scope ordering: this CTA's stores visible to this CTA's atomics.
    __syncthreads();

    // ---------------- Phase 3: slice-restricted masked scatter-add ----------------
    const int vsz = *vocab_size_p;
    const int lo  = slice * SLICE_F;
    const int hi  = lo + SLICE_F;
    const int*   ids = src_ids   + (size_t)row * T_DIM;
    const float* at  = attn_dist + (size_t)row * T_DIM;

    #pragma unroll
    for (int t = tid; t < T_DIM; t += NT) {
        const int id = ids[t];
        if (id < vsz && id >= lo && id < hi) {
            atomicAdd(out + (size_t)row * V_DIM + id, pc * at[t]);
        }
    }
}

extern "C" void kernel_launch(void* const* d_in, const int* in_sizes, int n_in,
                              void* d_out, int out_size) {
    const float* vocab_dist = (const float*)d_in[0];
    const float* attn_dist  = (const float*)d_in[1];
    const float* context    = (const float*)d_in[2];
    const float* state      = (const float*)d_in[3];
    const float* emb        = (const float*)d_in[4];
    const int*   src_ids    = (const int*)d_in[5];
    const int*   vocab_size = (const int*)d_in[6];
    const float* w_c        = (const float*)d_in[7];
    const float* w_s        = (const float*)d_in[8];
    const float* w_y        = (const float*)d_in[9];
    const float* b          = (const float*)d_in[10];
    float*       out        = (float*)d_out;

    pointer_generator_fused<<<B_DIM * SLICES, NT>>>(
        vocab_dist, attn_dist, context, state, emb, src_ids, vocab_size,
        w_c, w_s, w_y, b, out);
}